// round 16
// baseline (speedup 1.0000x reference)
#include <cuda_runtime.h>
#include <cuda_fp16.h>
#include <math.h>
#include <stdint.h>

#define Hdim   4096
#define Edim   64
#define TOKS   64
#define KC     32                    // K elems per chunk
#define NCHUNK (Hdim / KC)           // 128
#define ABYTES   4096                // 64 rows * 64 B (fp16 x 32)
#define BBYTES   4096                // 64 rows * 64 B
#define BUF_BYTES (ABYTES + BBYTES)  // 8192
#define DYN_SMEM  18944              // max(2*BUF_BYTES, 64*LPITCH*4 logits)
#define NT     256
#define LPITCH 72
#define TAU 4e-3f
#define QMAX 16

#define MMAH(d, a, b0_, b1_)                                                  \
    asm volatile("mma.sync.aligned.m16n8k16.row.col.f32.f16.f16.f32 "         \
                 "{%0,%1,%2,%3},{%4,%5,%6,%7},{%8,%9},{%0,%1,%2,%3};"         \
                 : "+f"((d)[0]), "+f"((d)[1]), "+f"((d)[2]), "+f"((d)[3])     \
                 : "r"((a)[0]), "r"((a)[1]), "r"((a)[2]), "r"((a)[3]),        \
                   "r"(b0_), "r"(b1_))

#define LDSM4(r, addr)                                                        \
    asm volatile("ldmatrix.sync.aligned.m8n8.x4.shared.b16 {%0,%1,%2,%3}, [%4];" \
                 : "=r"((r)[0]), "=r"((r)[1]), "=r"((r)[2]), "=r"((r)[3])     \
                 : "r"(addr))

__device__ __forceinline__ uint32_t packhf(float lo, float hi) {
    __half2 h = __floats2half2_rn(lo, hi);
    return *(uint32_t*)&h;
}

__global__ __launch_bounds__(NT, 2)
void router_mma(const float* __restrict__ x, const float* __restrict__ W,
                float* __restrict__ out, int T)
{
    extern __shared__ __align__(16) char dsm[];
    __shared__ float s_max[TOKS];
    __shared__ float s_inv[TOKS];
    __shared__ int      s_qn;
    __shared__ int      s_qt[QMAX];
    __shared__ unsigned s_qp[QMAX];

    const int tid  = threadIdx.x;
    const int wid  = tid >> 5;
    const int lane = tid & 31;
    const int q    = lane >> 2;
    const int cc   = lane & 3;
    const int wm   = wid >> 1;           // 0..3 : 16-token warp tile
    const int wn   = wid & 1;            // 0..1 : 32-expert warp tile
    const int tb   = blockIdx.x * TOKS;

    const uint32_t sbase = (uint32_t)__cvta_generic_to_shared(dsm);

    const int rB = tid >> 3;             // loader row base (0..31)
    const int s4 = tid & 7;              // loader 8B segment within 64B row

    if (tid == 0) s_qn = 0;

    auto soff = [&](int r) -> uint32_t {
        return (uint32_t)(r * 64 + ((((s4 >> 1) + (r >> 1)) & 3) << 4) + ((s4 & 1) << 3));
    };

    // 3 register staging sets: LDG(c+3) issued at iter c, consumed at iter c+2
    float4 ra[3][2]; float4 rb[3][2];

    auto ldg_chunk = [&](int c, int s) {
        const int kb = c * KC + s4 * 4;
#pragma unroll
        for (int p = 0; p < 2; p++)
            ra[s][p] = *(const float4*)(x + (size_t)(tb + rB + 32 * p) * Hdim + kb);
#pragma unroll
        for (int p = 0; p < 2; p++)
            rb[s][p] = *(const float4*)(W + (size_t)(rB + 32 * p) * Hdim + kb);
    };

    auto cvt_sts = [&](int b, int s) {
        char* buf = dsm + b * BUF_BYTES;
#pragma unroll
        for (int p = 0; p < 2; p++) {
            float4 f = ra[s][p];
            *(uint2*)(buf + soff(rB + 32 * p)) =
                make_uint2(packhf(f.x, f.y), packhf(f.z, f.w));
        }
#pragma unroll
        for (int p = 0; p < 2; p++) {
            float4 f = rb[s][p];
            *(uint2*)(buf + ABYTES + soff(rB + 32 * p)) =
                make_uint2(packhf(f.x, f.y), packhf(f.z, f.w));
        }
    };

    float acc[4][4];
#pragma unroll
    for (int j = 0; j < 4; j++)
#pragma unroll
        for (int r = 0; r < 4; r++) acc[j][r] = 0.0f;

    const int arow = wm * 16 + (lane & 7) + ((lane >> 3) & 1) * 8;
    const int brow = wn * 32 + lane;

    ldg_chunk(0, 0);
    ldg_chunk(1, 1);
    ldg_chunk(2, 2);
    cvt_sts(0, 0);
    __syncthreads();

    for (int c = 0; c < NCHUNK; c++) {
        // 1) deep prefetch: chunk c+3 into set (c+3)%3 (freed by cvt of chunk c)
        if (c + 3 < NCHUNK) ldg_chunk(c + 3, (c + 3) % 3);
        // 2) convert+store chunk c+1 (LDG landed 2 iterations ago)
        if (c + 1 < NCHUNK) cvt_sts((c + 1) & 1, (c + 1) % 3);

        // 3) MMA on chunk c
        const uint32_t Ah = sbase + (c & 1) * BUF_BYTES;
        const uint32_t Bh = Ah + ABYTES;
#pragma unroll
        for (int ks = 0; ks < 2; ks++) {
            const int au = 2 * ks + (lane >> 4);
            const uint32_t aoff = (uint32_t)(arow * 64 + (((au + (arow >> 1)) & 3) << 4));
            const uint32_t bo0  = (uint32_t)(brow * 64 + ((((2*ks)   + (brow >> 1)) & 3) << 4));
            const uint32_t bo1  = (uint32_t)(brow * 64 + ((((2*ks+1) + (brow >> 1)) & 3) << 4));

            uint32_t ah[4], bh0[4], bh1[4];
            LDSM4(ah, Ah + aoff);
            LDSM4(bh0, Bh + bo0);
            LDSM4(bh1, Bh + bo1);
#pragma unroll
            for (int j = 0; j < 4; j++) MMAH(acc[j], ah, bh0[j], bh1[j]);
        }
        __syncthreads();
    }

    // -------- epilogue: logits -> smem, fused softmax/top-2 + near-tie queue --------
    float* ls = (float*)dsm;
#pragma unroll
    for (int j = 0; j < 4; j++) {
        int row = wm * 16 + q;
        int col = wn * 32 + j * 8 + 2 * cc;
        *(float2*)(ls + row * LPITCH + col)       = make_float2(acc[j][0], acc[j][1]);
        *(float2*)(ls + (row + 8) * LPITCH + col) = make_float2(acc[j][2], acc[j][3]);
    }
    __syncthreads();

    float* scores_out = out;
    float* w_out = out + (size_t)T * Edim;
    float* i_out = w_out + (size_t)T * 2;

    if (tid < TOKS) {
        const float* row = ls + tid * LPITCH;
        float m = -INFINITY;
#pragma unroll
        for (int e = 0; e < Edim; e++) m = fmaxf(m, row[e]);

        float Z = 0.0f;
        float v0=-INFINITY, v1=-INFINITY, v2=-INFINITY, v3=-INFINITY;
        int   i0=0, i1=0, i2=0, i3=0;
#pragma unroll
        for (int e = 0; e < Edim; e++) {
            float v = row[e];
            Z += __expf(v - m);
            if (v > v0)      { v3=v2;i3=i2; v2=v1;i2=i1; v1=v0;i1=i0; v0=v;i0=e; }
            else if (v > v1) { v3=v2;i3=i2; v2=v1;i2=i1; v1=v;i1=e; }
            else if (v > v2) { v3=v2;i3=i2; v2=v;i2=e; }
            else if (v > v3) { v3=v;i3=e; }
        }
        s_max[tid] = m;
        s_inv[tid] = 1.0f / Z;

        float e0 = __expf(v0 - m);
        float e1 = __expf(v1 - m);
        float rs = 1.0f / (e0 + e1);
        size_t gt = (size_t)(tb + tid);
        w_out[gt * 2 + 0] = e0 * rs;
        w_out[gt * 2 + 1] = e1 * rs;
        i_out[gt * 2 + 0] = (float)i0;
        i_out[gt * 2 + 1] = (float)i1;

        if ((v0 - v1 < TAU) || (v1 - v2 < TAU)) {
            int slot = atomicAdd(&s_qn, 1);
            if (slot < QMAX) {
                s_qt[slot] = tid;
                s_qp[slot] = (unsigned)(i0 | (i1 << 6) | (i2 << 12) | (i3 << 18));
            }
        }
    }
    __syncthreads();

#pragma unroll
    for (int p = 0; p < (TOKS * Edim) / NT; p++) {
        int idx = tid + p * NT;
        int t = idx >> 6, e = idx & 63;
        scores_out[(size_t)(tb + t) * Edim + e] =
            __expf(ls[t * LPITCH + e] - s_max[t]) * s_inv[t];
    }

    // -------- in-CTA exact fixup: one warp per near-tie token --------
    const int nq = (s_qn < QMAX) ? s_qn : QMAX;
    for (int it = wid; it < nq; it += 8) {
        const int lt = s_qt[it];
        const unsigned pk = s_qp[it];
        const float4* xr = (const float4*)(x + (size_t)(tb + lt) * Hdim);
        float v[4];
#pragma unroll
        for (int cand = 0; cand < 4; cand++) {
            const int ej = (pk >> (6 * cand)) & 63;
            const float4* wr = (const float4*)(W + (size_t)ej * Hdim);
            float a = 0.0f;
#pragma unroll 4
            for (int i = lane; i < Hdim / 4; i += 32) {
                float4 xv = xr[i];
                float4 wv = wr[i];
                a += xv.x * wv.x + xv.y * wv.y + xv.z * wv.z + xv.w * wv.w;
            }
#pragma unroll
            for (int o = 16; o; o >>= 1) a += __shfl_xor_sync(0xFFFFFFFFu, a, o);
            v[cand] = a;
        }
        if (lane == 0) {
            int id[4];
#pragma unroll
            for (int j = 0; j < 4; j++) id[j] = (int)((pk >> (6 * j)) & 63);
            int b0 = 0;
#pragma unroll
            for (int j = 1; j < 4; j++)
                if (v[j] > v[b0] || (v[j] == v[b0] && id[j] < id[b0])) b0 = j;
            int b1 = (b0 == 0) ? 1 : 0;
#pragma unroll
            for (int j = 0; j < 4; j++)
                if (j != b0 && (v[j] > v[b1] || (v[j] == v[b1] && id[j] < id[b1]))) b1 = j;
            float er  = __expf(v[b1] - v[b0]);
            float inv = 1.0f / (1.0f + er);
            size_t gt = (size_t)(tb + lt);
            w_out[gt * 2 + 0] = inv;
            w_out[gt * 2 + 1] = er * inv;
            i_out[gt * 2 + 0] = (float)id[b0];
            i_out[gt * 2 + 1] = (float)id[b1];
        }
    }
}

extern "C" void kernel_launch(void* const* d_in, const int* in_sizes, int n_in,
                              void* d_out, int out_size)
{
    const float* x = (const float*)d_in[0];
    const float* W = (const float*)d_in[1];
    float* out = (float*)d_out;
    const int T = in_sizes[0] / Hdim;            // 16384
    cudaFuncSetAttribute(router_mma, cudaFuncAttributeMaxDynamicSharedMemorySize, DYN_SMEM);
    router_mma<<<T / TOKS, NT, DYN_SMEM>>>(x, W, out, T);
}

// round 17
// speedup vs baseline: 2.1433x; 2.1433x over previous
#include <cuda_runtime.h>
#include <cuda_fp16.h>
#include <math.h>
#include <stdint.h>

#define Hdim   4096
#define Edim   64
#define TOKS   128
#define KC     32                    // K elems per chunk
#define NCHUNK (Hdim / KC)           // 128
#define ABYTES   8192                // 128 rows * 64 B (fp16 x 32)
#define BBYTES   4096                // 64 rows * 64 B
#define BUF_BYTES (ABYTES + BBYTES)  // 12288
#define DYN_SMEM  36864              // max(2*BUF_BYTES, 128*72*4 logits)
#define NT     256
#define LPITCH 72
#define TAU 4e-3f
#define QMAX 32

#define MMAH(d, a, b0_, b1_)                                                  \
    asm volatile("mma.sync.aligned.m16n8k16.row.col.f32.f16.f16.f32 "         \
                 "{%0,%1,%2,%3},{%4,%5,%6,%7},{%8,%9},{%0,%1,%2,%3};"         \
                 : "+f"((d)[0]), "+f"((d)[1]), "+f"((d)[2]), "+f"((d)[3])     \
                 : "r"((a)[0]), "r"((a)[1]), "r"((a)[2]), "r"((a)[3]),        \
                   "r"(b0_), "r"(b1_))

#define LDSM4(r, addr)                                                        \
    asm volatile("ldmatrix.sync.aligned.m8n8.x4.shared.b16 {%0,%1,%2,%3}, [%4];" \
                 : "=r"((r)[0]), "=r"((r)[1]), "=r"((r)[2]), "=r"((r)[3])     \
                 : "r"(addr))

__device__ __forceinline__ uint32_t packhf(float lo, float hi) {
    __half2 h = __floats2half2_rn(lo, hi);
    return *(uint32_t*)&h;
}

__global__ __launch_bounds__(NT)
void router_mma(const float* __restrict__ x, const float* __restrict__ W,
                float* __restrict__ out, int T)
{
    extern __shared__ __align__(16) char dsm[];
    __shared__ float s_max[TOKS];
    __shared__ float s_inv[TOKS];
    __shared__ int      s_qn;
    __shared__ int      s_qt[QMAX];
    __shared__ unsigned s_qp[QMAX];

    const int tid  = threadIdx.x;
    const int wid  = tid >> 5;
    const int lane = tid & 31;
    const int q    = lane >> 2;
    const int cc   = lane & 3;
    const int wm   = wid >> 1;           // 0..3 : 32-token warp tile
    const int wn   = wid & 1;            // 0..1 : 32-expert warp tile
    const int tb   = blockIdx.x * TOKS;

    const uint32_t sbase = (uint32_t)__cvta_generic_to_shared(dsm);

    const int rB = tid >> 3;             // loader row base (0..31)
    const int s4 = tid & 7;              // loader 8B segment within 64B row

    if (tid == 0) s_qn = 0;

    auto soff = [&](int r) -> uint32_t {
        return (uint32_t)(r * 64 + ((((s4 >> 1) + (r >> 1)) & 3) << 4) + ((s4 & 1) << 3));
    };

    // two NAMED staging sets (compile-time identity): E = even chunks, O = odd
    float4 raE[4], rbE[2], raO[4], rbO[2];

    auto ldgE = [&](int c) {
        const int kb = c * KC + s4 * 4;
#pragma unroll
        for (int p = 0; p < 4; p++)
            raE[p] = *(const float4*)(x + (size_t)(tb + rB + 32 * p) * Hdim + kb);
#pragma unroll
        for (int p = 0; p < 2; p++)
            rbE[p] = *(const float4*)(W + (size_t)(rB + 32 * p) * Hdim + kb);
    };
    auto ldgO = [&](int c) {
        const int kb = c * KC + s4 * 4;
#pragma unroll
        for (int p = 0; p < 4; p++)
            raO[p] = *(const float4*)(x + (size_t)(tb + rB + 32 * p) * Hdim + kb);
#pragma unroll
        for (int p = 0; p < 2; p++)
            rbO[p] = *(const float4*)(W + (size_t)(rB + 32 * p) * Hdim + kb);
    };

    auto cvtE = [&](int b) {
        char* buf = dsm + b * BUF_BYTES;
#pragma unroll
        for (int p = 0; p < 4; p++) {
            float4 f = raE[p];
            *(uint2*)(buf + soff(rB + 32 * p)) =
                make_uint2(packhf(f.x, f.y), packhf(f.z, f.w));
        }
#pragma unroll
        for (int p = 0; p < 2; p++) {
            float4 f = rbE[p];
            *(uint2*)(buf + ABYTES + soff(rB + 32 * p)) =
                make_uint2(packhf(f.x, f.y), packhf(f.z, f.w));
        }
    };
    auto cvtO = [&](int b) {
        char* buf = dsm + b * BUF_BYTES;
#pragma unroll
        for (int p = 0; p < 4; p++) {
            float4 f = raO[p];
            *(uint2*)(buf + soff(rB + 32 * p)) =
                make_uint2(packhf(f.x, f.y), packhf(f.z, f.w));
        }
#pragma unroll
        for (int p = 0; p < 2; p++) {
            float4 f = rbO[p];
            *(uint2*)(buf + ABYTES + soff(rB + 32 * p)) =
                make_uint2(packhf(f.x, f.y), packhf(f.z, f.w));
        }
    };

    float acc[2][4][4];
#pragma unroll
    for (int mt = 0; mt < 2; mt++)
#pragma unroll
        for (int j = 0; j < 4; j++)
#pragma unroll
            for (int r = 0; r < 4; r++) acc[mt][j][r] = 0.0f;

    const int arow = wm * 32 + (lane & 7) + ((lane >> 3) & 1) * 8;  // + mt*16
    const int brow = wn * 32 + lane;

    auto mma_chunk = [&](int b) {
        const uint32_t Ah = sbase + b * BUF_BYTES;
        const uint32_t Bh = Ah + ABYTES;
#pragma unroll
        for (int ks = 0; ks < 2; ks++) {
            const int au = 2 * ks + (lane >> 4);
            const uint32_t aoff = (uint32_t)(arow * 64 + (((au + (arow >> 1)) & 3) << 4));
            const uint32_t bo0  = (uint32_t)(brow * 64 + ((((2*ks)   + (brow >> 1)) & 3) << 4));
            const uint32_t bo1  = (uint32_t)(brow * 64 + ((((2*ks+1) + (brow >> 1)) & 3) << 4));
            uint32_t ah0[4], ah1[4], bh0[4], bh1[4];
            LDSM4(ah0, Ah + aoff);
            LDSM4(ah1, Ah + aoff + 1024);
            LDSM4(bh0, Bh + bo0);
            LDSM4(bh1, Bh + bo1);
#pragma unroll
            for (int j = 0; j < 4; j++) MMAH(acc[0][j], ah0, bh0[j], bh1[j]);
#pragma unroll
            for (int j = 0; j < 4; j++) MMAH(acc[1][j], ah1, bh0[j], bh1[j]);
        }
    };

    // prologue: E=chunk0, O=chunk1; cvt chunk0; E=chunk2
    ldgE(0);
    ldgO(1);
    cvtE(0);
    ldgE(2);
    __syncthreads();

    // steady state, unroll 2: LDG issued phase c is consumed phase c+2
    for (int c = 0; c < NCHUNK; c += 2) {
        // phase c (even): MMA buf0; cvt chunk c+1 (from O) -> buf1; ldg c+3 -> O
        if (c + 1 < NCHUNK) cvtO(1);
        if (c + 3 < NCHUNK) ldgO(c + 3);
        mma_chunk(0);
        __syncthreads();

        // phase c+1 (odd): MMA buf1; cvt chunk c+2 (from E) -> buf0; ldg c+4 -> E
        if (c + 1 < NCHUNK) {
            if (c + 2 < NCHUNK) cvtE(0);
            if (c + 4 < NCHUNK) ldgE(c + 4);
            mma_chunk(1);
            __syncthreads();
        }
    }

    // -------- epilogue: logits -> smem, fused softmax/top-2 + near-tie queue --------
    float* ls = (float*)dsm;
#pragma unroll
    for (int mt = 0; mt < 2; mt++)
#pragma unroll
        for (int j = 0; j < 4; j++) {
            int row = wm * 32 + mt * 16 + q;
            int col = wn * 32 + j * 8 + 2 * cc;
            *(float2*)(ls + row * LPITCH + col)       = make_float2(acc[mt][j][0], acc[mt][j][1]);
            *(float2*)(ls + (row + 8) * LPITCH + col) = make_float2(acc[mt][j][2], acc[mt][j][3]);
        }
    __syncthreads();

    float* scores_out = out;
    float* w_out = out + (size_t)T * Edim;
    float* i_out = w_out + (size_t)T * 2;

    if (tid < TOKS) {
        const float* row = ls + tid * LPITCH;
        float m = -INFINITY;
#pragma unroll
        for (int e = 0; e < Edim; e++) m = fmaxf(m, row[e]);

        float Z = 0.0f;
        float v0=-INFINITY, v1=-INFINITY, v2=-INFINITY, v3=-INFINITY;
        int   i0=0, i1=0, i2=0, i3=0;
#pragma unroll
        for (int e = 0; e < Edim; e++) {
            float v = row[e];
            Z += __expf(v - m);
            if (v > v0)      { v3=v2;i3=i2; v2=v1;i2=i1; v1=v0;i1=i0; v0=v;i0=e; }
            else if (v > v1) { v3=v2;i3=i2; v2=v1;i2=i1; v1=v;i1=e; }
            else if (v > v2) { v3=v2;i3=i2; v2=v;i2=e; }
            else if (v > v3) { v3=v;i3=e; }
        }
        s_max[tid] = m;
        s_inv[tid] = 1.0f / Z;

        float e0 = __expf(v0 - m);
        float e1 = __expf(v1 - m);
        float rs = 1.0f / (e0 + e1);
        size_t gt = (size_t)(tb + tid);
        w_out[gt * 2 + 0] = e0 * rs;
        w_out[gt * 2 + 1] = e1 * rs;
        i_out[gt * 2 + 0] = (float)i0;
        i_out[gt * 2 + 1] = (float)i1;

        if ((v0 - v1 < TAU) || (v1 - v2 < TAU)) {
            int slot = atomicAdd(&s_qn, 1);
            if (slot < QMAX) {
                s_qt[slot] = tid;
                s_qp[slot] = (unsigned)(i0 | (i1 << 6) | (i2 << 12) | (i3 << 18));
            }
        }
    }
    __syncthreads();

#pragma unroll
    for (int p = 0; p < (TOKS * Edim) / NT; p++) {
        int idx = tid + p * NT;
        int t = idx >> 6, e = idx & 63;
        scores_out[(size_t)(tb + t) * Edim + e] =
            __expf(ls[t * LPITCH + e] - s_max[t]) * s_inv[t];
    }

    // -------- in-CTA exact fixup: one warp per near-tie token --------
    const int nq = (s_qn < QMAX) ? s_qn : QMAX;
    for (int it = wid; it < nq; it += 8) {
        const int lt = s_qt[it];
        const unsigned pk = s_qp[it];
        const float4* xr = (const float4*)(x + (size_t)(tb + lt) * Hdim);
        float v[4];
#pragma unroll
        for (int cand = 0; cand < 4; cand++) {
            const int ej = (pk >> (6 * cand)) & 63;
            const float4* wr = (const float4*)(W + (size_t)ej * Hdim);
            float a = 0.0f;
#pragma unroll 4
            for (int i = lane; i < Hdim / 4; i += 32) {
                float4 xv = xr[i];
                float4 wv = wr[i];
                a += xv.x * wv.x + xv.y * wv.y + xv.z * wv.z + xv.w * wv.w;
            }
#pragma unroll
            for (int o = 16; o; o >>= 1) a += __shfl_xor_sync(0xFFFFFFFFu, a, o);
            v[cand] = a;
        }
        if (lane == 0) {
            int id[4];
#pragma unroll
            for (int j = 0; j < 4; j++) id[j] = (int)((pk >> (6 * j)) & 63);
            int b0 = 0;
#pragma unroll
            for (int j = 1; j < 4; j++)
                if (v[j] > v[b0] || (v[j] == v[b0] && id[j] < id[b0])) b0 = j;
            int b1 = (b0 == 0) ? 1 : 0;
#pragma unroll
            for (int j = 0; j < 4; j++)
                if (j != b0 && (v[j] > v[b1] || (v[j] == v[b1] && id[j] < id[b1]))) b1 = j;
            float er  = __expf(v[b1] - v[b0]);
            float inv = 1.0f / (1.0f + er);
            size_t gt = (size_t)(tb + lt);
            w_out[gt * 2 + 0] = inv;
            w_out[gt * 2 + 1] = er * inv;
            i_out[gt * 2 + 0] = (float)id[b0];
            i_out[gt * 2 + 1] = (float)id[b1];
        }
    }
}

extern "C" void kernel_launch(void* const* d_in, const int* in_sizes, int n_in,
                              void* d_out, int out_size)
{
    const float* x = (const float*)d_in[0];
    const float* W = (const float*)d_in[1];
    float* out = (float*)d_out;
    const int T = in_sizes[0] / Hdim;            // 16384
    cudaFuncSetAttribute(router_mma, cudaFuncAttributeMaxDynamicSharedMemorySize, DYN_SMEM);
    router_mma<<<T / TOKS, NT, DYN_SMEM>>>(x, W, out, T);
}